// round 4
// baseline (speedup 1.0000x reference)
#include <cuda_runtime.h>
#include <stdint.h>

// ---------------------------------------------------------------------------
// Problem constants
// ---------------------------------------------------------------------------
#define EE   1000000
#define ND   10000
#define NT   20000
#define NRR  100
#define DD   64
#define SAMP 16

// JAX PRNG flavor: 1 = threefry_partitionable (modern default), 0 = original
#define PRNG_PARTITIONABLE 1

// ---------------------------------------------------------------------------
// Scratch (no allocs allowed -> __device__ globals)
// ---------------------------------------------------------------------------
__device__ float              g_score[EE];
__device__ unsigned long long g_keys[EE];
__device__ int                g_deg[ND];
__device__ int                g_off[ND];
__device__ int                g_cur[ND];
__device__ float              g_neigh[ND * DD];
__device__ float              g_y[ND * DD];
__device__ float              g_w1t[DD * DD];
__device__ float              g_w2rs[DD];
__device__ float              g_b2sum[1];
__device__ double             g_sum[DD];
__device__ double             g_sumsq[DD];
__device__ float              g_scale[DD];
__device__ float              g_shift[DD];

// ---------------------------------------------------------------------------
// Threefry-2x32 (20 rounds) — shared host/device
// ---------------------------------------------------------------------------
__host__ __device__ __forceinline__ void tf2x32(uint32_t k0, uint32_t k1,
                                                uint32_t x0, uint32_t x1,
                                                uint32_t& o0, uint32_t& o1)
{
    uint32_t ks[3];
    ks[0] = k0; ks[1] = k1; ks[2] = k0 ^ k1 ^ 0x1BD11BDAu;
    const int RA[4] = {13, 15, 26, 6};
    const int RB[4] = {17, 29, 16, 24};
    x0 += ks[0]; x1 += ks[1];
#pragma unroll
    for (int g = 0; g < 5; ++g) {
        const int* R = (g & 1) ? RB : RA;
#pragma unroll
        for (int i = 0; i < 4; ++i) {
            x0 += x1;
            int r = R[i];
            x1 = (x1 << r) | (x1 >> (32 - r));
            x1 ^= x0;
        }
        x0 += ks[(g + 1) % 3];
        x1 += ks[(g + 2) % 3] + (uint32_t)(g + 1);
    }
    o0 = x0; o1 = x1;
}

// 32-bit random draw at 64-bit counter position (hi, lo), matching JAX.
__host__ __device__ __forceinline__ uint32_t jax_bits32(uint32_t k0, uint32_t k1,
                                                        uint32_t hi, uint32_t lo)
{
    uint32_t o0, o1;
    tf2x32(k0, k1, hi, lo, o0, o1);
#if PRNG_PARTITIONABLE
    return o0 ^ o1;   // _threefry_random_bits_partitionable, bit_width==32
#else
    return o1;        // unused in original mode (different counter scheme)
#endif
}

// ---------------------------------------------------------------------------
// Packed f32x2 FMA helpers (FFMA2 — 2x fp32 throughput on sm_103a)
// ---------------------------------------------------------------------------
__device__ __forceinline__ unsigned long long pk2(float lo, float hi)
{
    unsigned long long r;
    asm("mov.b64 %0, {%1, %2};" : "=l"(r) : "f"(lo), "f"(hi));
    return r;
}
__device__ __forceinline__ void fma2(unsigned long long& acc,
                                     unsigned long long a, unsigned long long b)
{
    asm("fma.rn.f32x2 %0, %1, %2, %0;" : "+l"(acc) : "l"(a), "l"(b));
}
__device__ __forceinline__ float2 up2(unsigned long long v)
{
    float lo, hi;
    asm("mov.b64 {%0, %1}, %2;" : "=f"(lo), "=f"(hi) : "l"(v));
    return make_float2(lo, hi);
}

// ---------------------------------------------------------------------------
// K0: zero counters, transpose W1, rowsum W2
// ---------------------------------------------------------------------------
__global__ void k_init(const float* __restrict__ W1, const float* __restrict__ W2,
                       const float* __restrict__ b2)
{
    int i = blockIdx.x * blockDim.x + threadIdx.x;
    if (i < ND) g_deg[i] = 0;
    if (i < DD * DD) {
        int r = i >> 6, c = i & 63;
        g_w1t[c * DD + r] = W1[i];   // w1t[k][i] = W1[i][k]
    }
    if (i < DD) {
        float s = 0.f;
        for (int j = 0; j < DD; ++j) s += W2[i * DD + j];
        g_w2rs[i] = s;
        g_sum[i] = 0.0; g_sumsq[i] = 0.0;
    }
    if (i == 0) {
        float s = 0.f;
        for (int j = 0; j < DD; ++j) s += b2[j];
        g_b2sum[0] = s;
    }
}

// ---------------------------------------------------------------------------
// K1: per-edge score = sigmoid((d⊙r)@W1 + b1) · rowsum(W2) + sum(b2)
//     + degree histogram. FFMA2 mainloop, W1^T broadcast from shared.
// ---------------------------------------------------------------------------
__global__ void __launch_bounds__(128) k_score(const float* __restrict__ drug_emb,
                                               const float* __restrict__ rel_emb,
                                               const float* __restrict__ b1,
                                               const int* __restrict__ dkg)
{
    __shared__ float sW[DD * DD];
    __shared__ float sB1[DD];
    __shared__ float sRS[DD];
    __shared__ float sB2;
    int t = threadIdx.x;
    for (int i = t; i < DD * DD / 4; i += 128)
        ((float4*)sW)[i] = ((const float4*)g_w1t)[i];
    if (t < DD) { sB1[t] = b1[t]; sRS[t] = g_w2rs[t]; }
    if (t == 0) sB2 = g_b2sum[0];
    __syncthreads();

    int e = blockIdx.x * 128 + t;
    if (e >= EE) return;
    int head = dkg[3 * e];
    int rel  = dkg[3 * e + 2];

    const float4* dp = (const float4*)(drug_emb + (size_t)head * DD);
    const float4* rp = (const float4*)(rel_emb + (size_t)rel * DD);
    unsigned long long h2[DD / 2];
#pragma unroll
    for (int q = 0; q < 16; ++q) {
        float4 a = dp[q], b = rp[q];
        h2[2 * q]     = pk2(a.x * b.x, a.y * b.y);
        h2[2 * q + 1] = pk2(a.z * b.z, a.w * b.w);
    }

    float score = sB2;
#pragma unroll 2
    for (int k = 0; k < DD; ++k) {
        const ulonglong2* wr = (const ulonglong2*)(sW + k * DD);
        unsigned long long acc = pk2(sB1[k], 0.f);
#pragma unroll
        for (int q = 0; q < 16; ++q) {
            ulonglong2 w = wr[q];
            fma2(acc, h2[2 * q], w.x);
            fma2(acc, h2[2 * q + 1], w.y);
        }
        float2 ah = up2(acc);
        float x = ah.x + ah.y;
        float z = 1.f / (1.f + __expf(-x));
        score += z * sRS[k];
    }
    g_score[e] = score;
    atomicAdd(&g_deg[head], 1);
}

// ---------------------------------------------------------------------------
// K2: exclusive scan of degrees -> CSR offsets (+ scatter cursors)
// ---------------------------------------------------------------------------
__global__ void k_scan()
{
    __shared__ int part[1024];
    int t = threadIdx.x;
    int v[10];
    int loc = 0;
#pragma unroll
    for (int q = 0; q < 10; ++q) {
        int idx = t * 10 + q;
        v[q] = (idx < ND) ? g_deg[idx] : 0;
        loc += v[q];
    }
    part[t] = loc;
    __syncthreads();
    for (int d = 1; d < 1024; d <<= 1) {
        int add = (t >= d) ? part[t - d] : 0;
        __syncthreads();
        part[t] += add;
        __syncthreads();
    }
    int run = part[t] - loc;  // exclusive prefix
#pragma unroll
    for (int q = 0; q < 10; ++q) {
        int idx = t * 10 + q;
        if (idx < ND) { g_off[idx] = run; g_cur[idx] = run; run += v[q]; }
    }
}

// ---------------------------------------------------------------------------
// K3: scatter edges into head buckets with sort key = (uniform_bits>>9, e)
//     (reproduces jnp.lexsort((r, head)) ordering exactly, incl. stability)
// ---------------------------------------------------------------------------
__global__ void k_scatter(const int* __restrict__ dkg, uint32_t ka, uint32_t kb)
{
    int e = blockIdx.x * blockDim.x + threadIdx.x;
    if (e >= EE) return;
    int head = dkg[3 * e];
    uint32_t bits;
#if PRNG_PARTITIONABLE
    bits = jax_bits32(ka, kb, 0u, (uint32_t)e);   // o0 ^ o1 of tf(key, hi(i), lo(i))
#else
    const uint32_t half = EE / 2;
    uint32_t j = (e < (int)half) ? (uint32_t)e : (uint32_t)e - half;
    uint32_t o0, o1;
    tf2x32(ka, kb, j, j + half, o0, o1);
    bits = (e < (int)half) ? o0 : o1;
#endif
    uint32_t m = bits >> 9;  // float order == (bits>>9) order
    int pos = atomicAdd(&g_cur[head], 1);
    g_keys[pos] = ((unsigned long long)m << 32) | (unsigned long long)(uint32_t)e;
}

// ---------------------------------------------------------------------------
// K4: warp-per-drug: select 16 smallest keys (== rank<16 in lexsort order),
//     accumulate neigh[d] = sum score[e] * tail_emb[tail[e]].
//     Handles deg<16 (+replacement extras) for exactness, though unreachable
//     at Poisson(100) degrees.
// ---------------------------------------------------------------------------
__global__ void __launch_bounds__(256) k_select(const int* __restrict__ dkg,
                                                const float* __restrict__ tail_emb,
                                                uint32_t ua, uint32_t ub,
                                                uint32_t uc, uint32_t ud)
{
    __shared__ unsigned int selE[8][SAMP];
    int wid = threadIdx.x >> 5, lane = threadIdx.x & 31;
    int d = blockIdx.x * 8 + wid;
    if (d >= ND) return;
    int deg = g_deg[d];
    int off = g_off[d];
    float ax = 0.f, ay = 0.f;

    if (deg > 0) {
        int nkeep = min(deg, SAMP);
        unsigned long long prev = 0;
        bool small = (deg <= 192);
        unsigned long long kreg[6];
        if (small) {
#pragma unroll
            for (int q = 0; q < 6; ++q) {
                int p = lane + q * 32;
                kreg[q] = (p < deg) ? g_keys[off + p] : ~0ull;
            }
        }
        for (int it = 0; it < nkeep; ++it) {
            unsigned long long best = ~0ull;
            if (small) {
#pragma unroll
                for (int q = 0; q < 6; ++q) {
                    unsigned long long kk = kreg[q];
                    if ((it == 0 || kk > prev) && kk < best) best = kk;
                }
            } else {
                for (int p = lane; p < deg; p += 32) {
                    unsigned long long kk = g_keys[off + p];
                    if ((it == 0 || kk > prev) && kk < best) best = kk;
                }
            }
#pragma unroll
            for (int s = 16; s; s >>= 1) {
                unsigned long long o = __shfl_xor_sync(0xffffffffu, best, s);
                if (o < best) best = o;
            }
            prev = best;
            unsigned int e = (unsigned int)best;
            if (deg < SAMP && lane == 0) selE[wid][it] = e;
            float sc = g_score[e];
            int tl = dkg[3 * (int)e + 1];
            float2 te = *(const float2*)(tail_emb + (size_t)tl * DD + 2 * lane);
            ax += sc * te.x; ay += sc * te.y;
        }
        if (deg < SAMP) {
            __syncwarp();
            int need = SAMP - deg;
            const uint32_t span = 2147483647u;
            for (int si = 0; si < need; ++si) {
                uint32_t flat = (uint32_t)(d * SAMP + si);
                uint32_t hi  = jax_bits32(ua, ub, 0u, flat);
                uint32_t lo2 = jax_bits32(uc, ud, 0u, flat);
                unsigned long long offv =
                    ((unsigned long long)(hi % span) * 2ull + (lo2 % span)) % span;
                unsigned int j = (unsigned int)(offv % (unsigned int)deg);
                unsigned int e = selE[wid][j];
                float sc = g_score[e];
                int tl = dkg[3 * (int)e + 1];
                float2 te = *(const float2*)(tail_emb + (size_t)tl * DD + 2 * lane);
                ax += sc * te.x; ay += sc * te.y;
            }
        }
    }
    g_neigh[d * DD + 2 * lane]     = ax;
    g_neigh[d * DD + 2 * lane + 1] = ay;
}

// ---------------------------------------------------------------------------
// K5: y = [drug_emb | neigh] @ Wc + bc, plus per-column sum/sumsq for BN
// ---------------------------------------------------------------------------
__global__ void __launch_bounds__(256) k_y(const float* __restrict__ drug_emb,
                                           const float* __restrict__ Wc,
                                           const float* __restrict__ bc)
{
    __shared__ float sWc[2 * DD * DD];   // 32 KB
    __shared__ float sb[DD];
    __shared__ float red[256];
    int t = threadIdx.x;
    for (int i = t; i < 2 * DD * DD; i += 256) sWc[i] = Wc[i];
    if (t < DD) sb[t] = bc[t];
    __syncthreads();

    int col = t & 63, grp = t >> 6;
    int base = blockIdx.x * 64;
    float s1 = 0.f, s2 = 0.f;
    for (int rr = 0; rr < 16; ++rr) {
        int row = base + rr * 4 + grp;
        if (row < ND) {
            const float* de = drug_emb + (size_t)row * DD;
            const float* ne = g_neigh + (size_t)row * DD;
            float a = sb[col];
#pragma unroll
            for (int i = 0; i < DD; ++i) a += de[i] * sWc[i * DD + col];
#pragma unroll
            for (int i = 0; i < DD; ++i) a += ne[i] * sWc[(DD + i) * DD + col];
            g_y[row * DD + col] = a;
            s1 += a; s2 += a * a;
        }
    }
    red[t] = s1; __syncthreads();
    if (t < 64)
        atomicAdd(&g_sum[t], (double)(red[t] + red[t + 64] + red[t + 128] + red[t + 192]));
    __syncthreads();
    red[t] = s2; __syncthreads();
    if (t < 64)
        atomicAdd(&g_sumsq[t], (double)(red[t] + red[t + 64] + red[t + 128] + red[t + 192]));
}

// ---------------------------------------------------------------------------
// K6: fold BN stats into scale/shift
// ---------------------------------------------------------------------------
__global__ void k_bn(const float* __restrict__ gamma, const float* __restrict__ beta)
{
    int t = threadIdx.x;
    if (t < DD) {
        double mean = g_sum[t] / (double)ND;
        double var = g_sumsq[t] / (double)ND - mean * mean;
        float sc = gamma[t] * rsqrtf((float)var + 1e-5f);
        g_scale[t] = sc;
        g_shift[t] = beta[t] - (float)mean * sc;
    }
}

// ---------------------------------------------------------------------------
// K7: assemble output (HFEmbeding | normalized y | X)
// ---------------------------------------------------------------------------
__global__ void k_out(const float* __restrict__ hfe, const float* __restrict__ X,
                      float* __restrict__ out, int out_size)
{
    int i = blockIdx.x * blockDim.x + threadIdx.x;
    if (i >= out_size) return;
    if (i < ND * DD) {
        out[i] = hfe[i];
    } else if (i < 2 * ND * DD) {
        int j = i - ND * DD;
        int c = j & 63;
        out[i] = g_y[j] * g_scale[c] + g_shift[c];
    } else {
        out[i] = X[i - 2 * ND * DD];
    }
}

// ---------------------------------------------------------------------------
// Launcher
// ---------------------------------------------------------------------------
extern "C" void kernel_launch(void* const* d_in, const int* in_sizes, int n_in,
                              void* d_out, int out_size)
{
    const float* HFE      = (const float*)d_in[0];
    const float* X        = (const float*)d_in[1];
    const float* drug_emb = (const float*)d_in[2];
    const float* rel_emb  = (const float*)d_in[3];
    const float* tail_emb = (const float*)d_in[4];
    const float* W1       = (const float*)d_in[5];
    const float* b1       = (const float*)d_in[6];
    const float* W2       = (const float*)d_in[7];
    const float* b2       = (const float*)d_in[8];
    const float* Wc       = (const float*)d_in[9];
    const float* bc       = (const float*)d_in[10];
    const float* gamma    = (const float*)d_in[11];
    const float* beta     = (const float*)d_in[12];
    const int*   dkg      = (const int*)d_in[13];

    // Derive jax.random.key(42) subkeys on host (pure arithmetic).
    uint32_t key0 = 0u, key1 = 42u;
    uint32_t k1a, k1b, k2a, k2b;
#if PRNG_PARTITIONABLE
    tf2x32(key0, key1, 0u, 0u, k1a, k1b);   // fold-like split -> subkey 0
    tf2x32(key0, key1, 0u, 1u, k2a, k2b);   // fold-like split -> subkey 1
#else
    {
        uint32_t a0, c0, a1, c1;
        tf2x32(key0, key1, 0u, 2u, a0, c0);
        tf2x32(key0, key1, 1u, 3u, a1, c1);
        k1a = a0; k1b = a1; k2a = c0; k2b = c1;
    }
#endif
    // split(k2) for the randint double-draw (dead path: deg>=16 a.s.)
    uint32_t r1a, r1b, r2a, r2b;
#if PRNG_PARTITIONABLE
    tf2x32(k2a, k2b, 0u, 0u, r1a, r1b);
    tf2x32(k2a, k2b, 0u, 1u, r2a, r2b);
#else
    {
        uint32_t a0, c0, a1, c1;
        tf2x32(k2a, k2b, 0u, 2u, a0, c0);
        tf2x32(k2a, k2b, 1u, 3u, a1, c1);
        r1a = a0; r1b = a1; r2a = c0; r2b = c1;
    }
#endif

    k_init<<<40, 256>>>(W1, W2, b2);
    k_score<<<(EE + 127) / 128, 128>>>(drug_emb, rel_emb, b1, dkg);
    k_scan<<<1, 1024>>>();
    k_scatter<<<(EE + 255) / 256, 256>>>(dkg, k1a, k1b);
    k_select<<<(ND + 7) / 8, 256>>>(dkg, tail_emb, r1a, r1b, r2a, r2b);
    k_y<<<(ND + 63) / 64, 256>>>(drug_emb, Wc, bc);
    k_bn<<<1, 64>>>(gamma, beta);
    k_out<<<(out_size + 255) / 256, 256>>>(HFE, X, (float*)d_out, out_size);
}

// round 10
// speedup vs baseline: 2.8201x; 2.8201x over previous
#include <cuda_runtime.h>
#include <stdint.h>

// ---------------------------------------------------------------------------
// Problem constants
// ---------------------------------------------------------------------------
#define EE   1000000
#define ND   10000
#define NT   20000
#define NRR  100
#define DD   64
#define SAMP 16
#define CAP  512         // per-head bucket capacity (deg ~ Poisson(100))
#define OVF  65536       // overflow list capacity (guaranteed-correct fallback)

// JAX PRNG flavor: 1 = threefry_partitionable (modern default)
#define PRNG_PARTITIONABLE 1

// ---------------------------------------------------------------------------
// Scratch (no allocs allowed -> __device__ globals)
// ---------------------------------------------------------------------------
__device__ unsigned long long g_keys[(size_t)ND * CAP];   // 41 MB bucketed keys
__device__ int                g_cur[ND];                  // bucket cursors == degrees
__device__ int                g_ovf_cnt;
__device__ int                g_ovf_head[OVF];
__device__ unsigned long long g_ovf_key[OVF];
__device__ unsigned int       g_sel[ND * SAMP];           // selected edge ids
__device__ float              g_selscore[ND * SAMP];      // their scores
__device__ float              g_neigh[ND * DD];
__device__ float              g_y[ND * DD];
__device__ float              g_w1t[DD * DD];
__device__ float              g_w2rs[DD];
__device__ float              g_b2sum[1];
__device__ double             g_sum[DD];
__device__ double             g_sumsq[DD];
__device__ float              g_scale[DD];
__device__ float              g_shift[DD];

// ---------------------------------------------------------------------------
// Threefry-2x32 (20 rounds) — shared host/device
// ---------------------------------------------------------------------------
__host__ __device__ __forceinline__ void tf2x32(uint32_t k0, uint32_t k1,
                                                uint32_t x0, uint32_t x1,
                                                uint32_t& o0, uint32_t& o1)
{
    uint32_t ks[3];
    ks[0] = k0; ks[1] = k1; ks[2] = k0 ^ k1 ^ 0x1BD11BDAu;
    const int RA[4] = {13, 15, 26, 6};
    const int RB[4] = {17, 29, 16, 24};
    x0 += ks[0]; x1 += ks[1];
#pragma unroll
    for (int g = 0; g < 5; ++g) {
        const int* R = (g & 1) ? RB : RA;
#pragma unroll
        for (int i = 0; i < 4; ++i) {
            x0 += x1;
            int r = R[i];
            x1 = (x1 << r) | (x1 >> (32 - r));
            x1 ^= x0;
        }
        x0 += ks[(g + 1) % 3];
        x1 += ks[(g + 2) % 3] + (uint32_t)(g + 1);
    }
    o0 = x0; o1 = x1;
}

__host__ __device__ __forceinline__ uint32_t jax_bits32(uint32_t k0, uint32_t k1,
                                                        uint32_t hi, uint32_t lo)
{
    uint32_t o0, o1;
    tf2x32(k0, k1, hi, lo, o0, o1);
    return o0 ^ o1;   // _threefry_random_bits_partitionable, bit_width==32
}

// ---------------------------------------------------------------------------
// Packed f32x2 FMA helpers (FFMA2 — 2x fp32 throughput on sm_103a)
// ---------------------------------------------------------------------------
__device__ __forceinline__ unsigned long long pk2(float lo, float hi)
{
    unsigned long long r;
    asm("mov.b64 %0, {%1, %2};" : "=l"(r) : "f"(lo), "f"(hi));
    return r;
}
__device__ __forceinline__ void fma2(unsigned long long& acc,
                                     unsigned long long a, unsigned long long b)
{
    asm("fma.rn.f32x2 %0, %1, %2, %0;" : "+l"(acc) : "l"(a), "l"(b));
}
__device__ __forceinline__ float2 up2(unsigned long long v)
{
    float lo, hi;
    asm("mov.b64 {%0, %1}, %2;" : "=f"(lo), "=f"(hi) : "l"(v));
    return make_float2(lo, hi);
}

// ---------------------------------------------------------------------------
// K0: zero cursors, transpose W1, rowsum W2
// ---------------------------------------------------------------------------
__global__ void k_init(const float* __restrict__ W1, const float* __restrict__ W2,
                       const float* __restrict__ b2)
{
    int i = blockIdx.x * blockDim.x + threadIdx.x;
    if (i < ND) g_cur[i] = 0;
    if (i < DD * DD) {
        int r = i >> 6, c = i & 63;
        g_w1t[c * DD + r] = W1[i];   // w1t[k][i] = W1[i][k]
    }
    if (i < DD) {
        float s = 0.f;
        for (int j = 0; j < DD; ++j) s += W2[i * DD + j];
        g_w2rs[i] = s;
        g_sum[i] = 0.0; g_sumsq[i] = 0.0;
    }
    if (i == 0) {
        float s = 0.f;
        for (int j = 0; j < DD; ++j) s += b2[j];
        g_b2sum[0] = s;
        g_ovf_cnt = 0;
    }
}

// ---------------------------------------------------------------------------
// K1: single-pass bucketed scatter of sort keys (bits>>9, edge_id).
//     Bucket cursor doubles as the degree count.
// ---------------------------------------------------------------------------
__global__ void k_scatter(const int* __restrict__ dkg, uint32_t ka, uint32_t kb)
{
    int e = blockIdx.x * blockDim.x + threadIdx.x;
    if (e >= EE) return;
    int head = dkg[3 * e];
    uint32_t bits = jax_bits32(ka, kb, 0u, (uint32_t)e);
    uint32_t m = bits >> 9;  // float order == (bits>>9) order
    unsigned long long key =
        ((unsigned long long)m << 32) | (unsigned long long)(uint32_t)e;
    int pos = atomicAdd(&g_cur[head], 1);
    if (pos < CAP) {
        g_keys[(size_t)head * CAP + pos] = key;
    } else {
        int o = atomicAdd(&g_ovf_cnt, 1);
        if (o < OVF) { g_ovf_head[o] = head; g_ovf_key[o] = key; }
    }
}

// ---------------------------------------------------------------------------
// K2: warp-per-drug: select the 16 smallest keys (== rank<16 in lexsort order)
//     and record their edge ids in sorted order.
// ---------------------------------------------------------------------------
__global__ void __launch_bounds__(256) k_select()
{
    int wid = threadIdx.x >> 5, lane = threadIdx.x & 31;
    int d = blockIdx.x * 8 + wid;
    if (d >= ND) return;
    int deg = g_cur[d];
    if (deg <= 0) return;
    int n = min(deg, CAP);
    int oc = min(g_ovf_cnt, OVF);
    int nkeep = min(deg, SAMP);
    const unsigned long long* bucket = g_keys + (size_t)d * CAP;

    unsigned long long prev = 0;
    bool small = (n <= 192) && (oc == 0);
    unsigned long long kreg[6];
    if (small) {
#pragma unroll
        for (int q = 0; q < 6; ++q) {
            int p = lane + q * 32;
            kreg[q] = (p < n) ? bucket[p] : ~0ull;
        }
    }
    for (int it = 0; it < nkeep; ++it) {
        unsigned long long best = ~0ull;
        if (small) {
#pragma unroll
            for (int q = 0; q < 6; ++q) {
                unsigned long long kk = kreg[q];
                if ((it == 0 || kk > prev) && kk < best) best = kk;
            }
        } else {
            for (int p = lane; p < n; p += 32) {
                unsigned long long kk = bucket[p];
                if ((it == 0 || kk > prev) && kk < best) best = kk;
            }
            for (int o = lane; o < oc; o += 32) {
                if (g_ovf_head[o] == d) {
                    unsigned long long kk = g_ovf_key[o];
                    if ((it == 0 || kk > prev) && kk < best) best = kk;
                }
            }
        }
#pragma unroll
        for (int s = 16; s; s >>= 1) {
            unsigned long long o = __shfl_xor_sync(0xffffffffu, best, s);
            if (o < best) best = o;
        }
        prev = best;
        if (lane == 0) g_sel[d * SAMP + it] = (unsigned int)best;
    }
}

// ---------------------------------------------------------------------------
// K3: score ONLY the selected edges (<= 160k of 1e6):
//     score = sigmoid((drug[d]⊙rel[rel])@W1 + b1) · rowsum(W2) + sum(b2)
// ---------------------------------------------------------------------------
__global__ void __launch_bounds__(128) k_score_sel(const float* __restrict__ drug_emb,
                                                   const float* __restrict__ rel_emb,
                                                   const float* __restrict__ b1,
                                                   const int* __restrict__ dkg)
{
    __shared__ float sW[DD * DD];
    __shared__ float sB1[DD];
    __shared__ float sRS[DD];
    __shared__ float sB2;
    int t = threadIdx.x;
    for (int i = t; i < DD * DD / 4; i += 128)
        ((float4*)sW)[i] = ((const float4*)g_w1t)[i];
    if (t < DD) { sB1[t] = b1[t]; sRS[t] = g_w2rs[t]; }
    if (t == 0) sB2 = g_b2sum[0];
    __syncthreads();

    int idx = blockIdx.x * 128 + t;
    if (idx >= ND * SAMP) return;
    int d = idx >> 4, i = idx & 15;
    int nkeep = min(g_cur[d], SAMP);
    if (i >= nkeep) { g_selscore[idx] = 0.f; return; }
    unsigned int e = g_sel[idx];
    int rel = dkg[3 * (int)e + 2];

    const float4* dp = (const float4*)(drug_emb + (size_t)d * DD);
    const float4* rp = (const float4*)(rel_emb + (size_t)rel * DD);
    unsigned long long h2[DD / 2];
#pragma unroll
    for (int q = 0; q < 16; ++q) {
        float4 a = dp[q], b = rp[q];
        h2[2 * q]     = pk2(a.x * b.x, a.y * b.y);
        h2[2 * q + 1] = pk2(a.z * b.z, a.w * b.w);
    }

    float score = sB2;
#pragma unroll 2
    for (int k = 0; k < DD; ++k) {
        const ulonglong2* wr = (const ulonglong2*)(sW + k * DD);
        unsigned long long acc = pk2(sB1[k], 0.f);
#pragma unroll
        for (int q = 0; q < 16; ++q) {
            ulonglong2 w = wr[q];
            fma2(acc, h2[2 * q], w.x);
            fma2(acc, h2[2 * q + 1], w.y);
        }
        float2 ah = up2(acc);
        float x = ah.x + ah.y;
        float z = 1.f / (1.f + __expf(-x));
        score += z * sRS[k];
    }
    g_selscore[idx] = score;
}

// ---------------------------------------------------------------------------
// K4: warp-per-drug: neigh[d] = sum_{i<nkeep} score_i * tail_emb[tail_i]
//     (+ with-replacement extras when deg < 16; unreachable at Poisson(100))
// ---------------------------------------------------------------------------
__global__ void __launch_bounds__(256) k_neigh(const int* __restrict__ dkg,
                                               const float* __restrict__ tail_emb,
                                               uint32_t ua, uint32_t ub,
                                               uint32_t uc, uint32_t ud)
{
    int wid = threadIdx.x >> 5, lane = threadIdx.x & 31;
    int d = blockIdx.x * 8 + wid;
    if (d >= ND) return;
    int deg = g_cur[d];
    int nkeep = min(deg, SAMP);
    float ax = 0.f, ay = 0.f;

    for (int i = 0; i < nkeep; ++i) {
        unsigned int e = g_sel[d * SAMP + i];
        float sc = g_selscore[d * SAMP + i];
        int tl = dkg[3 * (int)e + 1];
        float2 te = *(const float2*)(tail_emb + (size_t)tl * DD + 2 * lane);
        ax += sc * te.x; ay += sc * te.y;
    }
    if (deg > 0 && deg < SAMP) {
        int need = SAMP - deg;
        const uint32_t span = 2147483647u;
        for (int si = 0; si < need; ++si) {
            uint32_t flat = (uint32_t)(d * SAMP + si);
            uint32_t hi  = jax_bits32(ua, ub, 0u, flat);
            uint32_t lo2 = jax_bits32(uc, ud, 0u, flat);
            unsigned long long offv =
                ((unsigned long long)(hi % span) * 2ull + (lo2 % span)) % span;
            unsigned int j = (unsigned int)(offv % (unsigned int)deg);
            unsigned int e = g_sel[d * SAMP + j];
            float sc = g_selscore[d * SAMP + j];
            int tl = dkg[3 * (int)e + 1];
            float2 te = *(const float2*)(tail_emb + (size_t)tl * DD + 2 * lane);
            ax += sc * te.x; ay += sc * te.y;
        }
    }
    g_neigh[d * DD + 2 * lane]     = ax;
    g_neigh[d * DD + 2 * lane + 1] = ay;
}

// ---------------------------------------------------------------------------
// K5: y = [drug_emb | neigh] @ Wc + bc, plus per-column sum/sumsq for BN
// ---------------------------------------------------------------------------
__global__ void __launch_bounds__(256) k_y(const float* __restrict__ drug_emb,
                                           const float* __restrict__ Wc,
                                           const float* __restrict__ bc)
{
    __shared__ float sWc[2 * DD * DD];   // 32 KB
    __shared__ float sb[DD];
    __shared__ float red[256];
    int t = threadIdx.x;
    for (int i = t; i < 2 * DD * DD; i += 256) sWc[i] = Wc[i];
    if (t < DD) sb[t] = bc[t];
    __syncthreads();

    int col = t & 63, grp = t >> 6;
    int base = blockIdx.x * 64;
    float s1 = 0.f, s2 = 0.f;
    for (int rr = 0; rr < 16; ++rr) {
        int row = base + rr * 4 + grp;
        if (row < ND) {
            const float* de = drug_emb + (size_t)row * DD;
            const float* ne = g_neigh + (size_t)row * DD;
            float a = sb[col];
#pragma unroll
            for (int i = 0; i < DD; ++i) a += de[i] * sWc[i * DD + col];
#pragma unroll
            for (int i = 0; i < DD; ++i) a += ne[i] * sWc[(DD + i) * DD + col];
            g_y[row * DD + col] = a;
            s1 += a; s2 += a * a;
        }
    }
    red[t] = s1; __syncthreads();
    if (t < 64)
        atomicAdd(&g_sum[t], (double)(red[t] + red[t + 64] + red[t + 128] + red[t + 192]));
    __syncthreads();
    red[t] = s2; __syncthreads();
    if (t < 64)
        atomicAdd(&g_sumsq[t], (double)(red[t] + red[t + 64] + red[t + 128] + red[t + 192]));
}

// ---------------------------------------------------------------------------
// K6: fold BN stats into scale/shift
// ---------------------------------------------------------------------------
__global__ void k_bn(const float* __restrict__ gamma, const float* __restrict__ beta)
{
    int t = threadIdx.x;
    if (t < DD) {
        double mean = g_sum[t] / (double)ND;
        double var = g_sumsq[t] / (double)ND - mean * mean;
        float sc = gamma[t] * rsqrtf((float)var + 1e-5f);
        g_scale[t] = sc;
        g_shift[t] = beta[t] - (float)mean * sc;
    }
}

// ---------------------------------------------------------------------------
// K7: assemble output (HFEmbeding | normalized y | X)
// ---------------------------------------------------------------------------
__global__ void k_out(const float* __restrict__ hfe, const float* __restrict__ X,
                      float* __restrict__ out, int out_size)
{
    int i = blockIdx.x * blockDim.x + threadIdx.x;
    if (i >= out_size) return;
    if (i < ND * DD) {
        out[i] = hfe[i];
    } else if (i < 2 * ND * DD) {
        int j = i - ND * DD;
        int c = j & 63;
        out[i] = g_y[j] * g_scale[c] + g_shift[c];
    } else {
        out[i] = X[i - 2 * ND * DD];
    }
}

// ---------------------------------------------------------------------------
// Launcher
// ---------------------------------------------------------------------------
extern "C" void kernel_launch(void* const* d_in, const int* in_sizes, int n_in,
                              void* d_out, int out_size)
{
    const float* HFE      = (const float*)d_in[0];
    const float* X        = (const float*)d_in[1];
    const float* drug_emb = (const float*)d_in[2];
    const float* rel_emb  = (const float*)d_in[3];
    const float* tail_emb = (const float*)d_in[4];
    const float* W1       = (const float*)d_in[5];
    const float* b1       = (const float*)d_in[6];
    const float* W2       = (const float*)d_in[7];
    const float* b2       = (const float*)d_in[8];
    const float* Wc       = (const float*)d_in[9];
    const float* bc       = (const float*)d_in[10];
    const float* gamma    = (const float*)d_in[11];
    const float* beta     = (const float*)d_in[12];
    const int*   dkg      = (const int*)d_in[13];

    // Derive jax.random.key(42) subkeys on host (pure arithmetic).
    uint32_t key0 = 0u, key1 = 42u;
    uint32_t k1a, k1b, k2a, k2b;
    tf2x32(key0, key1, 0u, 0u, k1a, k1b);   // fold-like split -> subkey 0
    tf2x32(key0, key1, 0u, 1u, k2a, k2b);   // fold-like split -> subkey 1
    // split(k2) for the randint double-draw (dead path: deg>=16 a.s.)
    uint32_t r1a, r1b, r2a, r2b;
    tf2x32(k2a, k2b, 0u, 0u, r1a, r1b);
    tf2x32(k2a, k2b, 0u, 1u, r2a, r2b);

    k_init<<<40, 256>>>(W1, W2, b2);
    k_scatter<<<(EE + 255) / 256, 256>>>(dkg, k1a, k1b);
    k_select<<<(ND + 7) / 8, 256>>>();
    k_score_sel<<<(ND * SAMP + 127) / 128, 128>>>(drug_emb, rel_emb, b1, dkg);
    k_neigh<<<(ND + 7) / 8, 256>>>(dkg, tail_emb, r1a, r1b, r2a, r2b);
    k_y<<<(ND + 63) / 64, 256>>>(drug_emb, Wc, bc);
    k_bn<<<1, 64>>>(gamma, beta);
    k_out<<<(out_size + 255) / 256, 256>>>(HFE, X, (float*)d_out, out_size);
}